// round 16
// baseline (speedup 1.0000x reference)
#include <cuda_runtime.h>
#include <cuda_fp16.h>
#include <math.h>
#include <stdint.h>

#define BATCH 8
#define SEQ   2048
#define DIM   512
#define NH    8
#define HD    64
#define BM    (BATCH*SEQ)   // 16384
#define HSZ   ((size_t)BATCH * NH * SEQ * HD)   // one q/k/v segment in halves

// ---------------- scratch (static device memory; no allocations allowed) ----
__device__ __align__(16) float  g_theta[256];
__device__ __align__(16) float  g_cs[SEQ][256][2];
__device__ __align__(16) __half g_x[(size_t)BM * DIM];
__device__ __align__(16) __half g_wq[DIM * DIM];
__device__ __align__(16) __half g_wk[DIM * DIM];
__device__ __align__(16) __half g_wv[DIM * DIM];
__device__ __align__(16) __half g_wip[3 * DIM * DIM];
__device__ __align__(16) __half g_wo[DIM * DIM];
__device__ __align__(16) __half g_YR[(size_t)BM * 1536];
__device__ __align__(16) __half g_QKV[3 * HSZ];   // Q,K: [b][h][pos][dd]; V: [b][h][dd][pos]
__device__ __align__(16) __half g_ctx[(size_t)BM * DIM];

// k-group-16 permutation: storage position of logical column c.
// perm = [0,1,8,9, 2,3,10,11, 4,5,12,13, 6,7,14,15]
// => LDS.64 at position 4*tg returns logical pairs (2tg,2tg+1) and (2tg+8,2tg+9).
__device__ __forceinline__ int pcol(int c) {
    return (c & ~15) | ((c & 6) << 1) | ((c & 8) >> 2) | (c & 1);
}

__device__ __forceinline__ uint32_t smem_u32(const void* p) {
    uint32_t a;
    asm("{ .reg .u64 t; cvta.to.shared.u64 t, %1; cvt.u32.u64 %0, t; }" : "=r"(a) : "l"(p));
    return a;
}
__device__ __forceinline__ void cp16(uint32_t dst, const void* src) {
    asm volatile("cp.async.cg.shared.global [%0], [%1], 16;" :: "r"(dst), "l"(src));
}
__device__ __forceinline__ void mma_f16(float d[4], const uint32_t a[4],
                                        uint32_t b0, uint32_t b1) {
    asm volatile(
        "mma.sync.aligned.m16n8k16.row.col.f32.f16.f16.f32 "
        "{%0,%1,%2,%3}, {%4,%5,%6,%7}, {%8,%9}, {%0,%1,%2,%3};"
        : "+f"(d[0]), "+f"(d[1]), "+f"(d[2]), "+f"(d[3])
        : "r"(a[0]), "r"(a[1]), "r"(a[2]), "r"(a[3]), "r"(b0), "r"(b1));
}
__device__ __forceinline__ uint32_t h2u(float lo, float hi) {
    __half2 h = __floats2half2_rn(lo, hi);
    return *reinterpret_cast<uint32_t*>(&h);
}

// ---------------- setup ------------------------------------------------------
__global__ void setup_theta_kernel() {
    int i = threadIdx.x;
    double e = -2.0 * ((double)i - 1.0) / 512.0;
    g_theta[i] = (float)pow(10000.0, e);
}
__global__ void setup_cs_kernel() {
    int pos = blockIdx.x;
    int i = threadIdx.x;
    float ang = (float)pos * g_theta[i];
    float s, c;
    sincosf(ang, &s, &c);
    g_cs[pos][i][0] = c;
    g_cs[pos][i][1] = s;
}

// one launch converts all fp32 inputs to fp16 scratch (k-permuted layout)
struct F2HJobs {
    const float4* src[6];
    __half2*      dst[6];
    int           n4[6];
};
__global__ void f2h_all_kernel(F2HJobs jobs) {
    const int stride = gridDim.x * blockDim.x;
    #pragma unroll
    for (int s = 0; s < 6; s++) {
        const float4* src = jobs.src[s];
        __half2* dst = jobs.dst[s];
        const int n4 = jobs.n4[s];
        for (int i = blockIdx.x * blockDim.x + threadIdx.x; i < n4; i += stride) {
            float4 v = src[i];
            int c = 4 * i;   // flat half index (rows are multiples of 16 -> safe)
            dst[pcol(c)     >> 1] = __floats2half2_rn(v.x, v.y);
            dst[pcol(c + 2) >> 1] = __floats2half2_rn(v.z, v.w);
        }
    }
}

// ---------------- 128x128-tile FP16 GEMM, LDS.64 fragments, k-chunk 64 -------
// MODE 0: YR = rope(g_x @ {wq,wk,wv}^T)         -> half (permuted cols)
// MODE 1: QKV = g_YR @ wip^T + b                -> half, scatter, Q scale, V transposed
// MODE 2: out = g_ctx @ wo^T + out_b            -> fp32 (logical cols)
#define PH 80                          // pitch in halves (160 B; LDS.64 conflict-free)
#define KCH 64                         // k-chunk (halves)
#define STAGE_H (128 * PH)             // halves per matrix per stage (10240)
#define GEMM_SMEM (2 * 2 * STAGE_H * 2)   // 81920 bytes

template<int MODE>
__global__ __launch_bounds__(256, 2) void gemm128h(
    const float* __restrict__ bias, float* __restrict__ Cout)
{
    extern __shared__ __half hsm[];

    const int m0  = blockIdx.y * 128;
    const int n0g = blockIdx.x * 128;
    const int seg = n0g >> 9;
    const int n0  = n0g & 511;

    const __half* Ap;
    const __half* Bp;
    int lda;
    if (MODE == 0) {
        const __half* Bsel = (seg == 0) ? g_wq : ((seg == 1) ? g_wk : g_wv);
        Bp = Bsel + (size_t)n0 * DIM;
        Ap = g_x + (size_t)m0 * DIM;  lda = DIM;
    } else if (MODE == 1) {
        Bp = g_wip + (size_t)n0g * DIM;
        Ap = g_YR + (size_t)m0 * 1536 + seg * DIM;  lda = 1536;
    } else {
        Bp = g_wo + (size_t)n0g * DIM;
        Ap = g_ctx + (size_t)m0 * DIM;  lda = DIM;
    }

    const int t    = threadIdx.x;
    const int warp = t >> 5, lane = t & 31;
    const int wr   = warp >> 2, wc = warp & 3;      // 2x4 warps, 64x32 each
    const int g    = lane >> 2, tg = lane & 3;

    const uint32_t sbase = smem_u32(hsm);

    float acc[4][4][4];
    #pragma unroll
    for (int mi = 0; mi < 4; mi++)
        #pragma unroll
        for (int ni = 0; ni < 4; ni++)
            #pragma unroll
            for (int r = 0; r < 4; r++) acc[mi][ni][r] = 0.f;

    // fill one stage: A and B tiles, 128 rows x 64 halves each (8x16B per row)
    auto issue_tile = [&](int slot, int k0) {
        uint32_t abase = sbase + (uint32_t)slot * 2 * STAGE_H * 2;
        uint32_t bbase = abase + STAGE_H * 2;
        #pragma unroll
        for (int it = 0; it < 4; it++) {
            int u = t + it * 256;          // 0..1023 16B units
            int row = u >> 3, c16 = u & 7;
            cp16(abase + (uint32_t)(row * (PH * 2) + c16 * 16),
                 Ap + (size_t)row * lda + k0 + c16 * 8);
            cp16(bbase + (uint32_t)(row * (PH * 2) + c16 * 16),
                 Bp + (size_t)row * DIM + k0 + c16 * 8);
        }
        asm volatile("cp.async.commit_group;");
    };

    issue_tile(0, 0);
    issue_tile(1, KCH);

    #pragma unroll 1
    for (int kt = 0; kt < 8; kt++) {
        if (kt < 7) {
            asm volatile("cp.async.wait_group 1;");
        } else {
            asm volatile("cp.async.wait_group 0;");
        }
        __syncthreads();

        const __half* As = hsm + (kt & 1) * 2 * STAGE_H;
        const __half* Bs = As + STAGE_H;
        const __half* Abase = As + (wr * 64 + g) * PH + 4 * tg;
        const __half* Bbase = Bs + (wc * 32 + g) * PH + 4 * tg;

        #pragma unroll
        for (int kb = 0; kb < 4; kb++) {
            const int kof = kb * 16;
            uint32_t a[4][4];
            #pragma unroll
            for (int mi = 0; mi < 4; mi++) {
                const __half* ap = Abase + mi * 16 * PH + kof;
                uint2 lo = *reinterpret_cast<const uint2*>(ap);            // a0,a2
                uint2 hi = *reinterpret_cast<const uint2*>(ap + 8 * PH);   // a1,a3
                a[mi][0] = lo.x; a[mi][1] = hi.x; a[mi][2] = lo.y; a[mi][3] = hi.y;
            }
            uint2 b[4];
            #pragma unroll
            for (int ni = 0; ni < 4; ni++)
                b[ni] = *reinterpret_cast<const uint2*>(Bbase + ni * 8 * PH + kof);
            #pragma unroll
            for (int mi = 0; mi < 4; mi++)
                #pragma unroll
                for (int ni = 0; ni < 4; ni++)
                    mma_f16(acc[mi][ni], a[mi], b[ni].x, b[ni].y);
        }
        __syncthreads();
        if (kt + 2 < 8) issue_tile(kt & 1, (kt + 2) * KCH);
    }

    // ---- fused epilogue ----
    const int gm_base = m0 + wr * 64;
    const int gn_base = n0g + wc * 32;

    #pragma unroll
    for (int mi = 0; mi < 4; mi++) {
        #pragma unroll
        for (int h = 0; h < 2; h++) {
            const int gm  = gm_base + mi * 16 + g + h * 8;
            const int pos = gm & (SEQ - 1);
            #pragma unroll
            for (int ni = 0; ni < 4; ni++) {
                float c0 = acc[mi][ni][2 * h];
                float c1 = acc[mi][ni][2 * h + 1];
                const int col = gn_base + ni * 8 + 2 * tg;
                if (MODE == 0) {
                    const int tp = (col & 511) >> 1;
                    float2 cs = *reinterpret_cast<const float2*>(&g_cs[pos][tp][0]);
                    float r0 =  c0 * cs.x + c1 * cs.y;
                    float r1 = -c0 * cs.y + c1 * cs.x;
                    *reinterpret_cast<uint32_t*>(&g_YR[(size_t)gm * 1536 + pcol(col)]) = h2u(r0, r1);
                } else if (MODE == 1) {
                    float2 bb = *reinterpret_cast<const float2*>(&bias[col]);
                    float v0 = c0 + bb.x, v1 = c1 + bb.y;
                    if (seg == 0) { v0 *= 0.125f; v1 *= 0.125f; }
                    const int batch = gm >> 11;
                    const int head  = (col & 511) >> 6;
                    const int dd    = col & 63;
                    if (seg < 2) {
                        size_t o = (size_t)seg * HSZ
                                 + ((size_t)(batch * NH + head) * SEQ + pos) * HD + pcol(dd);
                        *reinterpret_cast<uint32_t*>(&g_QKV[o]) = h2u(v0, v1);
                    } else {
                        size_t o = 2 * HSZ + ((size_t)(batch * NH + head) * HD + dd) * SEQ + pcol(pos);
                        g_QKV[o]       = __float2half_rn(v0);
                        g_QKV[o + SEQ] = __float2half_rn(v1);
                    }
                } else {
                    float2 bb = *reinterpret_cast<const float2*>(&bias[col]);
                    *reinterpret_cast<float2*>(&Cout[(size_t)gm * DIM + col]) =
                        make_float2(c0 + bb.x, c1 + bb.y);
                }
            }
        }
    }
}

// ---------------- flash attention v4: 128-key tiles, l via ones-column MMA ---
#define FP  80                             // K tile pitch in halves (160 B)
#define FPV 144                            // V^T tile pitch in halves (288 B)
#define FLASH_SMEM (2 * (128 * FP + 64 * FPV) * 2)   // 77824 B
#define ONES2 0x3C003C00u                  // half2(1.0, 1.0)

__global__ void __launch_bounds__(256, 2) flash4_kernel()
{
    extern __shared__ __half fsm[];
    __half* Ksb = fsm;                     // [2][128][FP]   (rows = keys)
    __half* Vsb = fsm + 2 * 128 * FP;      // [2][64][FPV]   (V^T: rows = hd, cols = 128 keys)

    const int bh = blockIdx.x;
    const int qt = 15 - blockIdx.y;        // heavy tiles first
    const int batch = bh >> 3, head = bh & 7;

    const int t = threadIdx.x;
    const int warp = t >> 5, lane = t & 31;
    const int g = lane >> 2, tg = lane & 3;
    const int base_r = warp * 16;
    const int qrow_lo = qt * 128 + base_r + g;
    const int qrow_hi = qrow_lo + 8;

    const __half* Qg = g_QKV + ((size_t)(batch * NH + head)) * SEQ * HD;
    const __half* Kg = g_QKV + HSZ + ((size_t)(batch * NH + head)) * SEQ * HD;
    const __half* Vg = g_QKV + 2 * HSZ + ((size_t)(batch * NH + head)) * HD * SEQ;

    const uint32_t ksb = smem_u32(Ksb);
    const uint32_t vsb = smem_u32(Vsb);

    // load 128 keys: K 128x64 halves, V^T 64x128 halves (both 1024 16B units)
    auto issue_kv = [&](int kt) {
        int buf = kt & 1;
        #pragma unroll
        for (int it = 0; it < 4; it++) {
            int u = t + it * 256;
            int kr = u >> 3, kc = u & 7;          // K: 8 units per 64-half row
            cp16(ksb + (uint32_t)(buf * 128 * FP + kr * FP) * 2 + kc * 16,
                 Kg + (size_t)kt * 128 * HD + (size_t)kr * HD + kc * 8);
            int vr = u >> 4, vc = u & 15;         // V: 16 units per 128-half row
            cp16(vsb + (uint32_t)(buf * 64 * FPV + vr * FPV) * 2 + vc * 16,
                 Vg + (size_t)vr * SEQ + kt * 128 + vc * 8);
        }
        asm volatile("cp.async.commit_group;");
    };

    const int nkt = qt + 1;
    issue_kv(0);

    // Q a-fragments: one uint2 per row per kb (permuted layout gives (a0,a2))
    uint32_t Qa[4][4];
    #pragma unroll
    for (int kb = 0; kb < 4; kb++) {
        uint2 qlo = *reinterpret_cast<const uint2*>(Qg + (size_t)qrow_lo * HD + kb * 16 + 4 * tg);
        uint2 qhi = *reinterpret_cast<const uint2*>(Qg + (size_t)qrow_hi * HD + kb * 16 + 4 * tg);
        Qa[kb][0] = qlo.x; Qa[kb][1] = qhi.x; Qa[kb][2] = qlo.y; Qa[kb][3] = qhi.y;
    }

    float O[8][4];
    #pragma unroll
    for (int n = 0; n < 8; n++) { O[n][0] = O[n][1] = O[n][2] = O[n][3] = 0.f; }
    float Ol[4] = {0.f, 0.f, 0.f, 0.f};    // ones-column accumulator: Ol[0]=l_lo, Ol[2]=l_hi
    float m_lo = -INFINITY, m_hi = -INFINITY;

    #pragma unroll 1
    for (int kt = 0; kt < nkt; kt++) {
        asm volatile("cp.async.wait_group 0;");
        __syncthreads();
        if (kt + 1 < nkt) issue_kv(kt + 1);

        const __half* Ks = Ksb + (kt & 1) * 128 * FP;
        const __half* Vs = Vsb + (kt & 1) * 64 * FPV;

        #pragma unroll
        for (int j = 0; j < 2; j++) {
            const int keybase = kt * 128 + j * 64;
            const __half* Ksj = Ks + j * 64 * FP;
            const __half* Vsj = Vs + j * 64;          // column offset into V^T

            // S = Q @ K^T
            float s[8][4];
            #pragma unroll
            for (int n = 0; n < 8; n++) { s[n][0] = s[n][1] = s[n][2] = s[n][3] = 0.f; }
            #pragma unroll
            for (int n = 0; n < 8; n++) {
                const __half* kb8 = Ksj + (n * 8 + g) * FP + 4 * tg;
                #pragma unroll
                for (int kb = 0; kb < 4; kb++) {
                    uint2 bb = *reinterpret_cast<const uint2*>(kb8 + kb * 16);
                    mma_f16(s[n], Qa[kb], bb.x, bb.y);
                }
            }

            // causal mask near diagonal
            if (keybase + 63 > qt * 128 + base_r) {
                #pragma unroll
                for (int n = 0; n < 8; n++) {
                    int gc0 = keybase + n * 8 + 2 * tg;
                    int gc1 = gc0 + 1;
                    if (gc0 > qrow_lo) s[n][0] = -1e30f;
                    if (gc1 > qrow_lo) s[n][1] = -1e30f;
                    if (gc0 > qrow_hi) s[n][2] = -1e30f;
                    if (gc1 > qrow_hi) s[n][3] = -1e30f;
                }
            }

            // online softmax max (fp32)
            float mx_lo = -1e30f, mx_hi = -1e30f;
            #pragma unroll
            for (int n = 0; n < 8; n++) {
                mx_lo = fmaxf(mx_lo, fmaxf(s[n][0], s[n][1]));
                mx_hi = fmaxf(mx_hi, fmaxf(s[n][2], s[n][3]));
            }
            mx_lo = fmaxf(mx_lo, __shfl_xor_sync(0xffffffffu, mx_lo, 1));
            mx_lo = fmaxf(mx_lo, __shfl_xor_sync(0xffffffffu, mx_lo, 2));
            mx_hi = fmaxf(mx_hi, __shfl_xor_sync(0xffffffffu, mx_hi, 1));
            mx_hi = fmaxf(mx_hi, __shfl_xor_sync(0xffffffffu, mx_hi, 2));

            float mnew_lo = fmaxf(m_lo, mx_lo);
            float mnew_hi = fmaxf(m_hi, mx_hi);
            float alpha_lo = __expf(m_lo - mnew_lo);
            float alpha_hi = __expf(m_hi - mnew_hi);
            m_lo = mnew_lo; m_hi = mnew_hi;

            // P a-fragments directly from registers (no sums, no smem)
            uint32_t Pa[4][4];
            #pragma unroll
            for (int kb = 0; kb < 4; kb++) {
                float p00 = __expf(s[2 * kb][0] - mnew_lo);
                float p01 = __expf(s[2 * kb][1] - mnew_lo);
                float p02 = __expf(s[2 * kb][2] - mnew_hi);
                float p03 = __expf(s[2 * kb][3] - mnew_hi);
                float p10 = __expf(s[2 * kb + 1][0] - mnew_lo);
                float p11 = __expf(s[2 * kb + 1][1] - mnew_lo);
                float p12 = __expf(s[2 * kb + 1][2] - mnew_hi);
                float p13 = __expf(s[2 * kb + 1][3] - mnew_hi);
                Pa[kb][0] = h2u(p00, p01);
                Pa[kb][1] = h2u(p02, p03);
                Pa[kb][2] = h2u(p10, p11);
                Pa[kb][3] = h2u(p12, p13);
            }

            #pragma unroll
            for (int n = 0; n < 8; n++) {
                O[n][0] *= alpha_lo; O[n][1] *= alpha_lo;
                O[n][2] *= alpha_hi; O[n][3] *= alpha_hi;
            }
            Ol[0] *= alpha_lo; Ol[2] *= alpha_hi;

            // O += P @ V   (B = V^T in smem: rows=hd, cols=key, key-permuted)
            #pragma unroll
            for (int n = 0; n < 8; n++) {
                const __half* vb8 = Vsj + (n * 8 + g) * FPV + 4 * tg;
                #pragma unroll
                for (int kb = 0; kb < 4; kb++) {
                    uint2 bb = *reinterpret_cast<const uint2*>(vb8 + kb * 16);
                    mma_f16(O[n], Pa[kb], bb.x, bb.y);
                }
            }
            // l += P @ ones  (every output column = row sum; no shuffle needed)
            #pragma unroll
            for (int kb = 0; kb < 4; kb++)
                mma_f16(Ol, Pa[kb], ONES2, ONES2);
        }
    }

    // epilogue: normalize, write half to g_ctx (permuted cols)
    float inv_lo = 1.f / Ol[0], inv_hi = 1.f / Ol[2];
    size_t row_lo = ((size_t)batch * SEQ + qrow_lo) * DIM + head * HD;
    size_t row_hi = row_lo + (size_t)8 * DIM;
    #pragma unroll
    for (int n = 0; n < 8; n++) {
        int sc = pcol(n * 8 + 2 * tg);
        *reinterpret_cast<uint32_t*>(&g_ctx[row_lo + sc]) =
            h2u(O[n][0] * inv_lo, O[n][1] * inv_lo);
        *reinterpret_cast<uint32_t*>(&g_ctx[row_hi + sc]) =
            h2u(O[n][2] * inv_hi, O[n][3] * inv_hi);
    }
}

// ---------------- launch ----------------------------------------------------
extern "C" void kernel_launch(void* const* d_in, const int* in_sizes, int n_in,
                              void* d_out, int out_size)
{
    const float* x         = (const float*)d_in[0];
    const float* w_q       = (const float*)d_in[1];
    const float* w_k       = (const float*)d_in[2];
    const float* w_v       = (const float*)d_in[3];
    const float* in_proj_w = (const float*)d_in[4];
    const float* in_proj_b = (const float*)d_in[5];
    const float* out_w     = (const float*)d_in[6];
    const float* out_b     = (const float*)d_in[7];
    float* out = (float*)d_out;

    void *p_x, *p_wq, *p_wk, *p_wv, *p_wip, *p_wo;
    cudaGetSymbolAddress(&p_x,   g_x);
    cudaGetSymbolAddress(&p_wq,  g_wq);
    cudaGetSymbolAddress(&p_wk,  g_wk);
    cudaGetSymbolAddress(&p_wv,  g_wv);
    cudaGetSymbolAddress(&p_wip, g_wip);
    cudaGetSymbolAddress(&p_wo,  g_wo);

    setup_theta_kernel<<<1, 256>>>();
    setup_cs_kernel<<<SEQ, 256>>>();

    F2HJobs jobs;
    jobs.src[0] = (const float4*)x;         jobs.dst[0] = (__half2*)p_x;   jobs.n4[0] = BM * DIM / 4;
    jobs.src[1] = (const float4*)in_proj_w; jobs.dst[1] = (__half2*)p_wip; jobs.n4[1] = 3 * DIM * DIM / 4;
    jobs.src[2] = (const float4*)w_q;       jobs.dst[2] = (__half2*)p_wq;  jobs.n4[2] = DIM * DIM / 4;
    jobs.src[3] = (const float4*)w_k;       jobs.dst[3] = (__half2*)p_wk;  jobs.n4[3] = DIM * DIM / 4;
    jobs.src[4] = (const float4*)w_v;       jobs.dst[4] = (__half2*)p_wv;  jobs.n4[4] = DIM * DIM / 4;
    jobs.src[5] = (const float4*)out_w;     jobs.dst[5] = (__half2*)p_wo;  jobs.n4[5] = DIM * DIM / 4;
    f2h_all_kernel<<<1184, 256>>>(jobs);

    cudaFuncSetAttribute(gemm128h<0>, cudaFuncAttributeMaxDynamicSharedMemorySize, GEMM_SMEM);
    cudaFuncSetAttribute(gemm128h<1>, cudaFuncAttributeMaxDynamicSharedMemorySize, GEMM_SMEM);
    cudaFuncSetAttribute(gemm128h<2>, cudaFuncAttributeMaxDynamicSharedMemorySize, GEMM_SMEM);
    cudaFuncSetAttribute(flash4_kernel, cudaFuncAttributeMaxDynamicSharedMemorySize, FLASH_SMEM);

    // rot(x @ W^T) for q,k,v  (N = 1536)
    gemm128h<0><<<dim3(12, 128), 256, GEMM_SMEM>>>(nullptr, nullptr);
    // in_proj + bias -> QKV (scatter, Q scaled, V transposed)
    gemm128h<1><<<dim3(12, 128), 256, GEMM_SMEM>>>(in_proj_b, nullptr);
    // causal flash attention -> g_ctx   (6th launch for ncu)
    flash4_kernel<<<dim3(64, 16), 256, FLASH_SMEM>>>();
    // out projection + bias -> d_out (fp32)
    gemm128h<2><<<dim3(4, 128), 256, GEMM_SMEM>>>(out_b, out);
}

// round 17
// speedup vs baseline: 1.0252x; 1.0252x over previous
#include <cuda_runtime.h>
#include <cuda_fp16.h>
#include <math.h>
#include <stdint.h>

#define BATCH 8
#define SEQ   2048
#define DIM   512
#define NH    8
#define HD    64
#define BM    (BATCH*SEQ)   // 16384
#define HSZ   ((size_t)BATCH * NH * SEQ * HD)   // one q/k/v segment in halves

// ---------------- scratch (static device memory; no allocations allowed) ----
__device__ __align__(16) float  g_cs[SEQ][256][2];
__device__ __align__(16) __half g_x[(size_t)BM * DIM];
__device__ __align__(16) __half g_wq[DIM * DIM];
__device__ __align__(16) __half g_wk[DIM * DIM];
__device__ __align__(16) __half g_wv[DIM * DIM];
__device__ __align__(16) __half g_wip[3 * DIM * DIM];
__device__ __align__(16) __half g_wo[DIM * DIM];
__device__ __align__(16) __half g_YR[(size_t)BM * 1536];
__device__ __align__(16) __half g_QKV[3 * HSZ];   // Q,K: [b][h][pos][dd]; V: [b][h][dd][pos]
__device__ __align__(16) __half g_ctx[(size_t)BM * DIM];

// k-group-16 permutation: storage position of logical column c.
// perm = [0,1,8,9, 2,3,10,11, 4,5,12,13, 6,7,14,15]
// => LDS.64 at position 4*tg returns logical pairs (2tg,2tg+1) and (2tg+8,2tg+9).
__device__ __forceinline__ int pcol(int c) {
    return (c & ~15) | ((c & 6) << 1) | ((c & 8) >> 2) | (c & 1);
}

__device__ __forceinline__ uint32_t smem_u32(const void* p) {
    uint32_t a;
    asm("{ .reg .u64 t; cvta.to.shared.u64 t, %1; cvt.u32.u64 %0, t; }" : "=r"(a) : "l"(p));
    return a;
}
__device__ __forceinline__ void cp16(uint32_t dst, const void* src) {
    asm volatile("cp.async.cg.shared.global [%0], [%1], 16;" :: "r"(dst), "l"(src));
}
__device__ __forceinline__ void mma_f16(float d[4], const uint32_t a[4],
                                        uint32_t b0, uint32_t b1) {
    asm volatile(
        "mma.sync.aligned.m16n8k16.row.col.f32.f16.f16.f32 "
        "{%0,%1,%2,%3}, {%4,%5,%6,%7}, {%8,%9}, {%0,%1,%2,%3};"
        : "+f"(d[0]), "+f"(d[1]), "+f"(d[2]), "+f"(d[3])
        : "r"(a[0]), "r"(a[1]), "r"(a[2]), "r"(a[3]), "r"(b0), "r"(b1));
}
__device__ __forceinline__ uint32_t h2u(float lo, float hi) {
    __half2 h = __floats2half2_rn(lo, hi);
    return *reinterpret_cast<uint32_t*>(&h);
}

// ---------------- fused prep: cos/sin table + all fp32->fp16 conversions -----
struct F2HJobs {
    const float4* src[6];
    __half2*      dst[6];
    int           n4[6];
};
#define PREP_GRID 1184
#define CS_BLOCKS 128

__global__ void prep_kernel(F2HJobs jobs) {
    const int b = blockIdx.x;
    const int tid = threadIdx.x;
    if (b < CS_BLOCKS) {
        // cos/sin table: block handles 16 positions; theta in smem (same double pow)
        __shared__ float s_theta[256];
        double e = -2.0 * ((double)tid - 1.0) / 512.0;
        s_theta[tid] = (float)pow(10000.0, e);
        __syncthreads();
        #pragma unroll 1
        for (int i = 0; i < 16; i++) {
            int pos = b * 16 + i;
            float ang = (float)pos * s_theta[tid];
            float s, c;
            sincosf(ang, &s, &c);
            g_cs[pos][tid][0] = c;
            g_cs[pos][tid][1] = s;
        }
    } else {
        // f2h conversions (k-permuted layout), grid-stride over remaining blocks
        const int stride = (PREP_GRID - CS_BLOCKS) * blockDim.x;
        const int base = (b - CS_BLOCKS) * blockDim.x + tid;
        #pragma unroll
        for (int s = 0; s < 6; s++) {
            const float4* src = jobs.src[s];
            __half2* dst = jobs.dst[s];
            const int n4 = jobs.n4[s];
            for (int i = base; i < n4; i += stride) {
                float4 v = src[i];
                int c = 4 * i;   // flat half index (rows are multiples of 16 -> safe)
                dst[pcol(c)     >> 1] = __floats2half2_rn(v.x, v.y);
                dst[pcol(c + 2) >> 1] = __floats2half2_rn(v.z, v.w);
            }
        }
    }
}

// ---------------- 128x128-tile FP16 GEMM, LDS.64 fragments, k-chunk 64 -------
// MODE 0: YR = rope(g_x @ {wq,wk,wv}^T)         -> half (permuted cols)
// MODE 1: QKV = g_YR @ wip^T + b                -> half, scatter, Q scale, V transposed
// MODE 2: out = g_ctx @ wo^T + out_b            -> fp32 (logical cols)
#define PH 80                          // pitch in halves (160 B; LDS.64 conflict-free)
#define KCH 64                         // k-chunk (halves)
#define STAGE_H (128 * PH)             // halves per matrix per stage (10240)
#define GEMM_SMEM (2 * 2 * STAGE_H * 2)   // 81920 bytes

template<int MODE>
__global__ __launch_bounds__(256, 2) void gemm128h(
    const float* __restrict__ bias, float* __restrict__ Cout)
{
    extern __shared__ __half hsm[];

    const int m0  = blockIdx.y * 128;
    const int n0g = blockIdx.x * 128;
    const int seg = n0g >> 9;
    const int n0  = n0g & 511;

    const __half* Ap;
    const __half* Bp;
    int lda;
    if (MODE == 0) {
        const __half* Bsel = (seg == 0) ? g_wq : ((seg == 1) ? g_wk : g_wv);
        Bp = Bsel + (size_t)n0 * DIM;
        Ap = g_x + (size_t)m0 * DIM;  lda = DIM;
    } else if (MODE == 1) {
        Bp = g_wip + (size_t)n0g * DIM;
        Ap = g_YR + (size_t)m0 * 1536 + seg * DIM;  lda = 1536;
    } else {
        Bp = g_wo + (size_t)n0g * DIM;
        Ap = g_ctx + (size_t)m0 * DIM;  lda = DIM;
    }

    const int t    = threadIdx.x;
    const int warp = t >> 5, lane = t & 31;
    const int wr   = warp >> 2, wc = warp & 3;      // 2x4 warps, 64x32 each
    const int g    = lane >> 2, tg = lane & 3;

    const uint32_t sbase = smem_u32(hsm);

    float acc[4][4][4];
    #pragma unroll
    for (int mi = 0; mi < 4; mi++)
        #pragma unroll
        for (int ni = 0; ni < 4; ni++)
            #pragma unroll
            for (int r = 0; r < 4; r++) acc[mi][ni][r] = 0.f;

    // fill one stage: A and B tiles, 128 rows x 64 halves each (8x16B per row)
    auto issue_tile = [&](int slot, int k0) {
        uint32_t abase = sbase + (uint32_t)slot * 2 * STAGE_H * 2;
        uint32_t bbase = abase + STAGE_H * 2;
        #pragma unroll
        for (int it = 0; it < 4; it++) {
            int u = t + it * 256;          // 0..1023 16B units
            int row = u >> 3, c16 = u & 7;
            cp16(abase + (uint32_t)(row * (PH * 2) + c16 * 16),
                 Ap + (size_t)row * lda + k0 + c16 * 8);
            cp16(bbase + (uint32_t)(row * (PH * 2) + c16 * 16),
                 Bp + (size_t)row * DIM + k0 + c16 * 8);
        }
        asm volatile("cp.async.commit_group;");
    };

    issue_tile(0, 0);
    issue_tile(1, KCH);

    #pragma unroll 1
    for (int kt = 0; kt < 8; kt++) {
        if (kt < 7) {
            asm volatile("cp.async.wait_group 1;");
        } else {
            asm volatile("cp.async.wait_group 0;");
        }
        __syncthreads();

        const __half* As = hsm + (kt & 1) * 2 * STAGE_H;
        const __half* Bs = As + STAGE_H;
        const __half* Abase = As + (wr * 64 + g) * PH + 4 * tg;
        const __half* Bbase = Bs + (wc * 32 + g) * PH + 4 * tg;

        #pragma unroll
        for (int kb = 0; kb < 4; kb++) {
            const int kof = kb * 16;
            uint32_t a[4][4];
            #pragma unroll
            for (int mi = 0; mi < 4; mi++) {
                const __half* ap = Abase + mi * 16 * PH + kof;
                uint2 lo = *reinterpret_cast<const uint2*>(ap);            // a0,a2
                uint2 hi = *reinterpret_cast<const uint2*>(ap + 8 * PH);   // a1,a3
                a[mi][0] = lo.x; a[mi][1] = hi.x; a[mi][2] = lo.y; a[mi][3] = hi.y;
            }
            uint2 b[4];
            #pragma unroll
            for (int ni = 0; ni < 4; ni++)
                b[ni] = *reinterpret_cast<const uint2*>(Bbase + ni * 8 * PH + kof);
            #pragma unroll
            for (int mi = 0; mi < 4; mi++)
                #pragma unroll
                for (int ni = 0; ni < 4; ni++)
                    mma_f16(acc[mi][ni], a[mi], b[ni].x, b[ni].y);
        }
        __syncthreads();
        if (kt + 2 < 8) issue_tile(kt & 1, (kt + 2) * KCH);
    }

    // ---- fused epilogue ----
    const int gm_base = m0 + wr * 64;
    const int gn_base = n0g + wc * 32;

    #pragma unroll
    for (int mi = 0; mi < 4; mi++) {
        #pragma unroll
        for (int h = 0; h < 2; h++) {
            const int gm  = gm_base + mi * 16 + g + h * 8;
            const int pos = gm & (SEQ - 1);
            #pragma unroll
            for (int ni = 0; ni < 4; ni++) {
                float c0 = acc[mi][ni][2 * h];
                float c1 = acc[mi][ni][2 * h + 1];
                const int col = gn_base + ni * 8 + 2 * tg;
                if (MODE == 0) {
                    const int tp = (col & 511) >> 1;
                    float2 cs = *reinterpret_cast<const float2*>(&g_cs[pos][tp][0]);
                    float r0 =  c0 * cs.x + c1 * cs.y;
                    float r1 = -c0 * cs.y + c1 * cs.x;
                    *reinterpret_cast<uint32_t*>(&g_YR[(size_t)gm * 1536 + pcol(col)]) = h2u(r0, r1);
                } else if (MODE == 1) {
                    float2 bb = *reinterpret_cast<const float2*>(&bias[col]);
                    float v0 = c0 + bb.x, v1 = c1 + bb.y;
                    if (seg == 0) { v0 *= 0.125f; v1 *= 0.125f; }
                    const int batch = gm >> 11;
                    const int head  = (col & 511) >> 6;
                    const int dd    = col & 63;
                    if (seg < 2) {
                        size_t o = (size_t)seg * HSZ
                                 + ((size_t)(batch * NH + head) * SEQ + pos) * HD + pcol(dd);
                        *reinterpret_cast<uint32_t*>(&g_QKV[o]) = h2u(v0, v1);
                    } else {
                        size_t o = 2 * HSZ + ((size_t)(batch * NH + head) * HD + dd) * SEQ + pcol(pos);
                        g_QKV[o]       = __float2half_rn(v0);
                        g_QKV[o + SEQ] = __float2half_rn(v1);
                    }
                } else {
                    float2 bb = *reinterpret_cast<const float2*>(&bias[col]);
                    *reinterpret_cast<float2*>(&Cout[(size_t)gm * DIM + col]) =
                        make_float2(c0 + bb.x, c1 + bb.y);
                }
            }
        }
    }
}

// ---------------- flash attention v4: 128-key tiles, l via ones-column MMA ---
#define FP  80                             // K tile pitch in halves (160 B)
#define FPV 144                            // V^T tile pitch in halves (288 B)
#define FLASH_SMEM (2 * (128 * FP + 64 * FPV) * 2)   // 77824 B
#define ONES2 0x3C003C00u                  // half2(1.0, 1.0)

__global__ void __launch_bounds__(256, 2) flash4_kernel()
{
    extern __shared__ __half fsm[];
    __half* Ksb = fsm;                     // [2][128][FP]   (rows = keys)
    __half* Vsb = fsm + 2 * 128 * FP;      // [2][64][FPV]   (V^T: rows = hd, cols = 128 keys)

    const int bh = blockIdx.x;
    const int qt = 15 - blockIdx.y;        // heavy tiles first
    const int batch = bh >> 3, head = bh & 7;

    const int t = threadIdx.x;
    const int warp = t >> 5, lane = t & 31;
    const int g = lane >> 2, tg = lane & 3;
    const int base_r = warp * 16;
    const int qrow_lo = qt * 128 + base_r + g;
    const int qrow_hi = qrow_lo + 8;

    const __half* Qg = g_QKV + ((size_t)(batch * NH + head)) * SEQ * HD;
    const __half* Kg = g_QKV + HSZ + ((size_t)(batch * NH + head)) * SEQ * HD;
    const __half* Vg = g_QKV + 2 * HSZ + ((size_t)(batch * NH + head)) * HD * SEQ;

    const uint32_t ksb = smem_u32(Ksb);
    const uint32_t vsb = smem_u32(Vsb);

    // load 128 keys: K 128x64 halves, V^T 64x128 halves (both 1024 16B units)
    auto issue_kv = [&](int kt) {
        int buf = kt & 1;
        #pragma unroll
        for (int it = 0; it < 4; it++) {
            int u = t + it * 256;
            int kr = u >> 3, kc = u & 7;          // K: 8 units per 64-half row
            cp16(ksb + (uint32_t)(buf * 128 * FP + kr * FP) * 2 + kc * 16,
                 Kg + (size_t)kt * 128 * HD + (size_t)kr * HD + kc * 8);
            int vr = u >> 4, vc = u & 15;         // V: 16 units per 128-half row
            cp16(vsb + (uint32_t)(buf * 64 * FPV + vr * FPV) * 2 + vc * 16,
                 Vg + (size_t)vr * SEQ + kt * 128 + vc * 8);
        }
        asm volatile("cp.async.commit_group;");
    };

    const int nkt = qt + 1;
    issue_kv(0);

    // Q a-fragments: one uint2 per row per kb (permuted layout gives (a0,a2))
    uint32_t Qa[4][4];
    #pragma unroll
    for (int kb = 0; kb < 4; kb++) {
        uint2 qlo = *reinterpret_cast<const uint2*>(Qg + (size_t)qrow_lo * HD + kb * 16 + 4 * tg);
        uint2 qhi = *reinterpret_cast<const uint2*>(Qg + (size_t)qrow_hi * HD + kb * 16 + 4 * tg);
        Qa[kb][0] = qlo.x; Qa[kb][1] = qhi.x; Qa[kb][2] = qlo.y; Qa[kb][3] = qhi.y;
    }

    float O[8][4];
    #pragma unroll
    for (int n = 0; n < 8; n++) { O[n][0] = O[n][1] = O[n][2] = O[n][3] = 0.f; }
    float Ol[4] = {0.f, 0.f, 0.f, 0.f};    // ones-column accumulator: Ol[0]=l_lo, Ol[2]=l_hi
    float m_lo = -INFINITY, m_hi = -INFINITY;

    #pragma unroll 1
    for (int kt = 0; kt < nkt; kt++) {
        asm volatile("cp.async.wait_group 0;");
        __syncthreads();
        if (kt + 1 < nkt) issue_kv(kt + 1);

        const __half* Ks = Ksb + (kt & 1) * 128 * FP;
        const __half* Vs = Vsb + (kt & 1) * 64 * FPV;

        #pragma unroll
        for (int j = 0; j < 2; j++) {
            const int keybase = kt * 128 + j * 64;
            const __half* Ksj = Ks + j * 64 * FP;
            const __half* Vsj = Vs + j * 64;          // column offset into V^T

            // S = Q @ K^T
            float s[8][4];
            #pragma unroll
            for (int n = 0; n < 8; n++) { s[n][0] = s[n][1] = s[n][2] = s[n][3] = 0.f; }
            #pragma unroll
            for (int n = 0; n < 8; n++) {
                const __half* kb8 = Ksj + (n * 8 + g) * FP + 4 * tg;
                #pragma unroll
                for (int kb = 0; kb < 4; kb++) {
                    uint2 bb = *reinterpret_cast<const uint2*>(kb8 + kb * 16);
                    mma_f16(s[n], Qa[kb], bb.x, bb.y);
                }
            }

            // causal mask near diagonal
            if (keybase + 63 > qt * 128 + base_r) {
                #pragma unroll
                for (int n = 0; n < 8; n++) {
                    int gc0 = keybase + n * 8 + 2 * tg;
                    int gc1 = gc0 + 1;
                    if (gc0 > qrow_lo) s[n][0] = -1e30f;
                    if (gc1 > qrow_lo) s[n][1] = -1e30f;
                    if (gc0 > qrow_hi) s[n][2] = -1e30f;
                    if (gc1 > qrow_hi) s[n][3] = -1e30f;
                }
            }

            // online softmax max (fp32)
            float mx_lo = -1e30f, mx_hi = -1e30f;
            #pragma unroll
            for (int n = 0; n < 8; n++) {
                mx_lo = fmaxf(mx_lo, fmaxf(s[n][0], s[n][1]));
                mx_hi = fmaxf(mx_hi, fmaxf(s[n][2], s[n][3]));
            }
            mx_lo = fmaxf(mx_lo, __shfl_xor_sync(0xffffffffu, mx_lo, 1));
            mx_lo = fmaxf(mx_lo, __shfl_xor_sync(0xffffffffu, mx_lo, 2));
            mx_hi = fmaxf(mx_hi, __shfl_xor_sync(0xffffffffu, mx_hi, 1));
            mx_hi = fmaxf(mx_hi, __shfl_xor_sync(0xffffffffu, mx_hi, 2));

            float mnew_lo = fmaxf(m_lo, mx_lo);
            float mnew_hi = fmaxf(m_hi, mx_hi);
            float alpha_lo = __expf(m_lo - mnew_lo);
            float alpha_hi = __expf(m_hi - mnew_hi);
            m_lo = mnew_lo; m_hi = mnew_hi;

            // P a-fragments directly from registers (no sums, no smem)
            uint32_t Pa[4][4];
            #pragma unroll
            for (int kb = 0; kb < 4; kb++) {
                float p00 = __expf(s[2 * kb][0] - mnew_lo);
                float p01 = __expf(s[2 * kb][1] - mnew_lo);
                float p02 = __expf(s[2 * kb][2] - mnew_hi);
                float p03 = __expf(s[2 * kb][3] - mnew_hi);
                float p10 = __expf(s[2 * kb + 1][0] - mnew_lo);
                float p11 = __expf(s[2 * kb + 1][1] - mnew_lo);
                float p12 = __expf(s[2 * kb + 1][2] - mnew_hi);
                float p13 = __expf(s[2 * kb + 1][3] - mnew_hi);
                Pa[kb][0] = h2u(p00, p01);
                Pa[kb][1] = h2u(p02, p03);
                Pa[kb][2] = h2u(p10, p11);
                Pa[kb][3] = h2u(p12, p13);
            }

            #pragma unroll
            for (int n = 0; n < 8; n++) {
                O[n][0] *= alpha_lo; O[n][1] *= alpha_lo;
                O[n][2] *= alpha_hi; O[n][3] *= alpha_hi;
            }
            Ol[0] *= alpha_lo; Ol[2] *= alpha_hi;

            // O += P @ V   (B = V^T in smem: rows=hd, cols=key, key-permuted)
            #pragma unroll
            for (int n = 0; n < 8; n++) {
                const __half* vb8 = Vsj + (n * 8 + g) * FPV + 4 * tg;
                #pragma unroll
                for (int kb = 0; kb < 4; kb++) {
                    uint2 bb = *reinterpret_cast<const uint2*>(vb8 + kb * 16);
                    mma_f16(O[n], Pa[kb], bb.x, bb.y);
                }
            }
            // l += P @ ones  (every output column = row sum; no shuffle needed)
            #pragma unroll
            for (int kb = 0; kb < 4; kb++)
                mma_f16(Ol, Pa[kb], ONES2, ONES2);
        }
    }

    // epilogue: normalize, write half to g_ctx (permuted cols)
    float inv_lo = 1.f / Ol[0], inv_hi = 1.f / Ol[2];
    size_t row_lo = ((size_t)batch * SEQ + qrow_lo) * DIM + head * HD;
    size_t row_hi = row_lo + (size_t)8 * DIM;
    #pragma unroll
    for (int n = 0; n < 8; n++) {
        int sc = pcol(n * 8 + 2 * tg);
        *reinterpret_cast<uint32_t*>(&g_ctx[row_lo + sc]) =
            h2u(O[n][0] * inv_lo, O[n][1] * inv_lo);
        *reinterpret_cast<uint32_t*>(&g_ctx[row_hi + sc]) =
            h2u(O[n][2] * inv_hi, O[n][3] * inv_hi);
    }
}

// ---------------- launch ----------------------------------------------------
extern "C" void kernel_launch(void* const* d_in, const int* in_sizes, int n_in,
                              void* d_out, int out_size)
{
    const float* x         = (const float*)d_in[0];
    const float* w_q       = (const float*)d_in[1];
    const float* w_k       = (const float*)d_in[2];
    const float* w_v       = (const float*)d_in[3];
    const float* in_proj_w = (const float*)d_in[4];
    const float* in_proj_b = (const float*)d_in[5];
    const float* out_w     = (const float*)d_in[6];
    const float* out_b     = (const float*)d_in[7];
    float* out = (float*)d_out;

    void *p_x, *p_wq, *p_wk, *p_wv, *p_wip, *p_wo;
    cudaGetSymbolAddress(&p_x,   g_x);
    cudaGetSymbolAddress(&p_wq,  g_wq);
    cudaGetSymbolAddress(&p_wk,  g_wk);
    cudaGetSymbolAddress(&p_wv,  g_wv);
    cudaGetSymbolAddress(&p_wip, g_wip);
    cudaGetSymbolAddress(&p_wo,  g_wo);

    F2HJobs jobs;
    jobs.src[0] = (const float4*)x;         jobs.dst[0] = (__half2*)p_x;   jobs.n4[0] = BM * DIM / 4;
    jobs.src[1] = (const float4*)in_proj_w; jobs.dst[1] = (__half2*)p_wip; jobs.n4[1] = 3 * DIM * DIM / 4;
    jobs.src[2] = (const float4*)w_q;       jobs.dst[2] = (__half2*)p_wq;  jobs.n4[2] = DIM * DIM / 4;
    jobs.src[3] = (const float4*)w_k;       jobs.dst[3] = (__half2*)p_wk;  jobs.n4[3] = DIM * DIM / 4;
    jobs.src[4] = (const float4*)w_v;       jobs.dst[4] = (__half2*)p_wv;  jobs.n4[4] = DIM * DIM / 4;
    jobs.src[5] = (const float4*)out_w;     jobs.dst[5] = (__half2*)p_wo;  jobs.n4[5] = DIM * DIM / 4;

    // fused prep: cos/sin table + all f2h conversions in ONE launch
    prep_kernel<<<PREP_GRID, 256>>>(jobs);

    cudaFuncSetAttribute(gemm128h<0>, cudaFuncAttributeMaxDynamicSharedMemorySize, GEMM_SMEM);
    cudaFuncSetAttribute(gemm128h<1>, cudaFuncAttributeMaxDynamicSharedMemorySize, GEMM_SMEM);
    cudaFuncSetAttribute(gemm128h<2>, cudaFuncAttributeMaxDynamicSharedMemorySize, GEMM_SMEM);
    cudaFuncSetAttribute(flash4_kernel, cudaFuncAttributeMaxDynamicSharedMemorySize, FLASH_SMEM);

    // rot(x @ W^T) for q,k,v  (N = 1536)
    gemm128h<0><<<dim3(12, 128), 256, GEMM_SMEM>>>(nullptr, nullptr);
    // in_proj + bias -> QKV (scatter, Q scaled, V transposed)
    gemm128h<1><<<dim3(12, 128), 256, GEMM_SMEM>>>(in_proj_b, nullptr);
    // causal flash attention -> g_ctx
    flash4_kernel<<<dim3(64, 16), 256, FLASH_SMEM>>>();
    // out projection + bias -> d_out (fp32)
    gemm128h<2><<<dim3(4, 128), 256, GEMM_SMEM>>>(out_b, out);
}